// round 1
// baseline (speedup 1.0000x reference)
#include <cuda_runtime.h>
#include <math.h>
#include <stdint.h>

static constexpr int B  = 4;
static constexpr int S  = 1024;
static constexpr int D  = 1024;
static constexpr int H  = 16;
static constexpr int HD = 64;
static constexpr int M  = 4096;
static constexpr int E  = 1024;
static constexpr int BS = B * S;
static constexpr float EPS = 1e-6f;

// ---------------- scratch (no allocations allowed -> device globals) -------
__device__ float g_xn    [(size_t)BS * D];          // 16 MB (reused for xn2)
__device__ float g_qkv   [(size_t)BS * 3 * D];      // 48 MB
__device__ float g_scores[(size_t)B * H * S * S];   // 256 MB
__device__ float g_ao    [(size_t)BS * D];          // 16 MB
__device__ float g_xmid  [(size_t)BS * D];          // 16 MB
__device__ float g_h     [(size_t)BS * 2 * M];      // 128 MB
__device__ float g_act   [(size_t)BS * M];          // 64 MB
__device__ float g_ss1   [B * 2 * D];
__device__ float g_ss2   [B * 2 * D];
__device__ float g_gates [B * 2 * D];

// ---------------- tiny emb GEMMs: out[b,n] = emb[b,:] @ W[:,n] + bias[n] ----
__global__ void emb_gemm3_kernel(const float* __restrict__ emb,
                                 const float* __restrict__ W0, const float* __restrict__ b0, float* __restrict__ o0,
                                 const float* __restrict__ W1, const float* __restrict__ b1, float* __restrict__ o1,
                                 const float* __restrict__ W2, const float* __restrict__ b2, float* __restrict__ o2)
{
    const float* W; const float* bias; float* out;
    if (blockIdx.z == 0)      { W = W0; bias = b0; out = o0; }
    else if (blockIdx.z == 1) { W = W1; bias = b1; out = o1; }
    else                      { W = W2; bias = b2; out = o2; }
    const int b  = blockIdx.y;
    const int nl = threadIdx.x & 63;
    const int n  = blockIdx.x * 64 + nl;
    const int ks = threadIdx.x >> 6;          // 4-way K split
    const float* er = emb + b * E;
    float acc = 0.f;
    #pragma unroll 4
    for (int k = ks * 256; k < ks * 256 + 256; k++)
        acc += er[k] * W[(size_t)k * (2 * D) + n];
    __shared__ float red[256];
    red[threadIdx.x] = acc;
    __syncthreads();
    if (ks == 0)
        out[b * 2 * D + n] = red[nl] + red[nl + 64] + red[nl + 128] + red[nl + 192] + bias[n];
}

// ---------------- adaLN modulate: out = rmsnorm(x)*w*(1+ss[:D]) + ss[D:] ----
__global__ void adaln_kernel(const float* __restrict__ x, const float* __restrict__ ss,
                             const float* __restrict__ w, float* __restrict__ out)
{
    const int r = blockIdx.x;
    const int b = r / S;
    const int t = threadIdx.x;
    const float4 v = *(const float4*)(x + (size_t)r * D + t * 4);
    float local = v.x * v.x + v.y * v.y + v.z * v.z + v.w * v.w;
    #pragma unroll
    for (int off = 16; off > 0; off >>= 1)
        local += __shfl_xor_sync(0xffffffffu, local, off);
    __shared__ float red[8];
    __shared__ float s_inv;
    if ((t & 31) == 0) red[t >> 5] = local;
    __syncthreads();
    if (t == 0) {
        float tot = 0.f;
        #pragma unroll
        for (int i = 0; i < 8; i++) tot += red[i];
        s_inv = 1.0f / (sqrtf(tot) * (1.0f / 32.0f) + EPS);   // /sqrt(D)
    }
    __syncthreads();
    const float inv = s_inv;
    const int j = t * 4;
    const float4 wv = *(const float4*)(w + j);
    const float4 sc = *(const float4*)(ss + b * 2 * D + j);
    const float4 sh = *(const float4*)(ss + b * 2 * D + D + j);
    float4 o;
    o.x = v.x * inv * wv.x * (1.f + sc.x) + sh.x;
    o.y = v.y * inv * wv.y * (1.f + sc.y) + sh.y;
    o.z = v.z * inv * wv.z * (1.f + sc.z) + sh.z;
    o.w = v.w * inv * wv.w * (1.f + sc.w) + sh.w;
    *(float4*)(out + (size_t)r * D + j) = o;
}

// ---------------- main fp32 GEMM: C = A[MxK] @ B[KxN] (+bias, +epilogue) ----
// EPI 0: C = AB + bias
// EPI 1: C = res + gate[row/S, col] * (AB + bias)     (gate row stride = 2*D)
template <int EPI>
__global__ void __launch_bounds__(256) gemm_kernel(
    const float* __restrict__ A, const float* __restrict__ Bm,
    const float* __restrict__ bias, float* __restrict__ C,
    const int Ndim, const int Kdim,
    const float* __restrict__ res, const float* __restrict__ gate)
{
    __shared__ float As[16][128];   // transposed A tile: As[k][m]
    __shared__ float Bs[16][128];   // Bs[k][n]
    const int tid = threadIdx.x;
    const int bm = blockIdx.y * 128;
    const int bn = blockIdx.x * 128;
    const int tx = tid & 15, ty = tid >> 4;
    float acc[8][8] = {};

    for (int k0 = 0; k0 < Kdim; k0 += 16) {
        #pragma unroll
        for (int i = 0; i < 2; i++) {
            const int f  = tid + i * 256;
            const int ar = f >> 2, ac = (f & 3) * 4;
            const float4 av = *(const float4*)(A + (size_t)(bm + ar) * Kdim + k0 + ac);
            As[ac + 0][ar] = av.x; As[ac + 1][ar] = av.y;
            As[ac + 2][ar] = av.z; As[ac + 3][ar] = av.w;
            const int br = f >> 5, bc = (f & 31) * 4;
            *(float4*)(&Bs[br][bc]) = *(const float4*)(Bm + (size_t)(k0 + br) * Ndim + bn + bc);
        }
        __syncthreads();
        #pragma unroll
        for (int k = 0; k < 16; k++) {
            float a[8], bb[8];
            *(float4*)(a)      = *(const float4*)(&As[k][ty * 8]);
            *(float4*)(a + 4)  = *(const float4*)(&As[k][ty * 8 + 4]);
            *(float4*)(bb)     = *(const float4*)(&Bs[k][tx * 8]);
            *(float4*)(bb + 4) = *(const float4*)(&Bs[k][tx * 8 + 4]);
            #pragma unroll
            for (int i = 0; i < 8; i++)
                #pragma unroll
                for (int j = 0; j < 8; j++)
                    acc[i][j] = fmaf(a[i], bb[j], acc[i][j]);
        }
        __syncthreads();
    }

    const int col = bn + tx * 8;
    float bc_[8];
    #pragma unroll
    for (int j = 0; j < 8; j++) bc_[j] = bias[col + j];
    #pragma unroll
    for (int i = 0; i < 8; i++) {
        const int row = bm + ty * 8 + i;
        float* cp = C + (size_t)row * Ndim + col;
        if (EPI == 0) {
            *(float4*)(cp)     = make_float4(acc[i][0] + bc_[0], acc[i][1] + bc_[1],
                                             acc[i][2] + bc_[2], acc[i][3] + bc_[3]);
            *(float4*)(cp + 4) = make_float4(acc[i][4] + bc_[4], acc[i][5] + bc_[5],
                                             acc[i][6] + bc_[6], acc[i][7] + bc_[7]);
        } else {
            const int bidx = row / S;
            const float* gp = gate + bidx * 2 * D + col;
            const float* rp = res + (size_t)row * Ndim + col;
            float o[8];
            #pragma unroll
            for (int j = 0; j < 8; j++)
                o[j] = rp[j] + gp[j] * (acc[i][j] + bc_[j]);
            *(float4*)(cp)     = make_float4(o[0], o[1], o[2], o[3]);
            *(float4*)(cp + 4) = make_float4(o[4], o[5], o[6], o[7]);
        }
    }
}

// ---------------- RoPE + per-head RMSNorm on q,k (in place in qkv) ----------
__global__ void rope_rms_kernel(float* __restrict__ qkv,
                                const float* __restrict__ nq_w,
                                const float* __restrict__ nk_w)
{
    const int id = blockIdx.x;          // ((b*S+s)*2 + t)*H + h
    const int h  = id & (H - 1);
    const int t  = (id >> 4) & 1;       // 0 = q, 1 = k
    const int bs = id >> 5;
    const int s  = bs & (S - 1);
    float* p = qkv + ((size_t)bs * 3 + t) * D + h * HD;
    const int d = threadIdx.x;          // 0..63
    const float xv = p[d];
    const int  i   = d & 31;
    // inv = 10000^(-i/32) = exp2(-i * log2(10000)/32)
    const float inv = exp2f(-(float)i * (13.287712379549449f / 32.0f));
    const float ang = (float)s * inv;
    float sn, cs;
    sincosf(ang, &sn, &cs);
    const float other = (d < 32) ? -p[d + 32] : p[d - 32];
    const float val = xv * cs + other * sn;
    __shared__ float red[64];
    red[d] = val * val;
    __syncthreads();
    if (d < 32) {
        float r = red[d] + red[d + 32];
        #pragma unroll
        for (int off = 16; off > 0; off >>= 1)
            r += __shfl_xor_sync(0xffffffffu, r, off);
        if (d == 0) red[0] = 1.0f / (sqrtf(r) * 0.125f + EPS);   // /sqrt(64)
    }
    __syncthreads();
    const float* w = (t == 0) ? nq_w : nk_w;
    p[d] = val * red[0] * w[d];
}

// ---------------- scores = (Q @ K^T) * HD^-0.5 -------------------------------
__global__ void attn_scores_kernel(const float* __restrict__ qkv, float* __restrict__ scores)
{
    const int bh = blockIdx.z;
    const int b = bh >> 4, h = bh & 15;
    const int q0 = blockIdx.y * 64, k0 = blockIdx.x * 64;
    __shared__ float Qs[64][64];   // [d][q]
    __shared__ float Ks[64][64];   // [d][k]
    const int tid = threadIdx.x;
    #pragma unroll
    for (int i = 0; i < 4; i++) {
        const int f   = tid + i * 256;
        const int row = f >> 4;
        const int dc  = (f & 15) * 4;
        const float4 qv = *(const float4*)(qkv + ((size_t)(b * S + q0 + row) * 3 + 0) * D + h * HD + dc);
        Qs[dc + 0][row] = qv.x; Qs[dc + 1][row] = qv.y; Qs[dc + 2][row] = qv.z; Qs[dc + 3][row] = qv.w;
        const float4 kv = *(const float4*)(qkv + ((size_t)(b * S + k0 + row) * 3 + 1) * D + h * HD + dc);
        Ks[dc + 0][row] = kv.x; Ks[dc + 1][row] = kv.y; Ks[dc + 2][row] = kv.z; Ks[dc + 3][row] = kv.w;
    }
    __syncthreads();
    const int tx = tid & 15, ty = tid >> 4;
    float acc[4][4] = {};
    #pragma unroll 16
    for (int d = 0; d < 64; d++) {
        const float4 a  = *(const float4*)(&Qs[d][ty * 4]);
        const float4 bv = *(const float4*)(&Ks[d][tx * 4]);
        const float av[4]  = {a.x, a.y, a.z, a.w};
        const float bvv[4] = {bv.x, bv.y, bv.z, bv.w};
        #pragma unroll
        for (int i = 0; i < 4; i++)
            #pragma unroll
            for (int j = 0; j < 4; j++)
                acc[i][j] = fmaf(av[i], bvv[j], acc[i][j]);
    }
    #pragma unroll
    for (int i = 0; i < 4; i++) {
        const float4 o = make_float4(acc[i][0] * 0.125f, acc[i][1] * 0.125f,
                                     acc[i][2] * 0.125f, acc[i][3] * 0.125f);
        *(float4*)(scores + ((size_t)bh * S + q0 + ty * 4 + i) * S + k0 + tx * 4) = o;
    }
}

// ---------------- row softmax over S=1024 ------------------------------------
__global__ void softmax_kernel(float* __restrict__ scores)
{
    float* p = scores + (size_t)blockIdx.x * S;
    const int t = threadIdx.x;
    float4 v = *((float4*)p + t);
    float mx = fmaxf(fmaxf(v.x, v.y), fmaxf(v.z, v.w));
    #pragma unroll
    for (int off = 16; off > 0; off >>= 1)
        mx = fmaxf(mx, __shfl_xor_sync(0xffffffffu, mx, off));
    __shared__ float red[8];
    __shared__ float bc;
    if ((t & 31) == 0) red[t >> 5] = mx;
    __syncthreads();
    if (t == 0) {
        float m = red[0];
        #pragma unroll
        for (int i = 1; i < 8; i++) m = fmaxf(m, red[i]);
        bc = m;
    }
    __syncthreads();
    const float m = bc;
    v.x = __expf(v.x - m); v.y = __expf(v.y - m);
    v.z = __expf(v.z - m); v.w = __expf(v.w - m);
    float sum = v.x + v.y + v.z + v.w;
    #pragma unroll
    for (int off = 16; off > 0; off >>= 1)
        sum += __shfl_xor_sync(0xffffffffu, sum, off);
    if ((t & 31) == 0) red[t >> 5] = sum;
    __syncthreads();
    if (t == 0) {
        float s = 0.f;
        #pragma unroll
        for (int i = 0; i < 8; i++) s += red[i];
        bc = 1.0f / s;
    }
    __syncthreads();
    const float inv = bc;
    v.x *= inv; v.y *= inv; v.z *= inv; v.w *= inv;
    *((float4*)p + t) = v;
}

// ---------------- ao = attn @ V ----------------------------------------------
__global__ void attn_av_kernel(const float* __restrict__ attn, const float* __restrict__ qkv,
                               float* __restrict__ ao)
{
    const int bh = blockIdx.y;
    const int b = bh >> 4, h = bh & 15;
    const int q0 = blockIdx.x * 64;
    const int tid = threadIdx.x;
    const int tx = tid & 15, ty = tid >> 4;
    __shared__ float Ast[64][64];   // [k][q]
    __shared__ float Vs[64][64];    // [k][d]
    float acc[4][4] = {};
    for (int kt = 0; kt < S; kt += 64) {
        #pragma unroll
        for (int i = 0; i < 4; i++) {
            const int f   = tid + i * 256;
            const int row = f >> 4;
            const int c4  = (f & 15) * 4;
            const float4 a = *(const float4*)(attn + ((size_t)bh * S + q0 + row) * S + kt + c4);
            Ast[c4 + 0][row] = a.x; Ast[c4 + 1][row] = a.y;
            Ast[c4 + 2][row] = a.z; Ast[c4 + 3][row] = a.w;
            const float4 vv = *(const float4*)(qkv + ((size_t)(b * S + kt + row) * 3 + 2) * D + h * HD + c4);
            *(float4*)(&Vs[row][c4]) = vv;
        }
        __syncthreads();
        #pragma unroll 16
        for (int k = 0; k < 64; k++) {
            const float4 a  = *(const float4*)(&Ast[k][ty * 4]);
            const float4 bv = *(const float4*)(&Vs[k][tx * 4]);
            const float av[4]  = {a.x, a.y, a.z, a.w};
            const float bvv[4] = {bv.x, bv.y, bv.z, bv.w};
            #pragma unroll
            for (int i = 0; i < 4; i++)
                #pragma unroll
                for (int j = 0; j < 4; j++)
                    acc[i][j] = fmaf(av[i], bvv[j], acc[i][j]);
        }
        __syncthreads();
    }
    #pragma unroll
    for (int i = 0; i < 4; i++) {
        const float4 o = make_float4(acc[i][0], acc[i][1], acc[i][2], acc[i][3]);
        *(float4*)(ao + ((size_t)(b * S + q0 + ty * 4 + i)) * D + h * HD + tx * 4) = o;
    }
}

// ---------------- SwiGLU: act = h[:, :M] * silu(h[:, M:]) --------------------
__global__ void silu_kernel(const float* __restrict__ hb, float* __restrict__ act)
{
    const size_t idx = (size_t)blockIdx.x * 256 + threadIdx.x;   // float4 units
    const size_t r = idx >> 10;              // M/4 = 1024 float4 per row
    const int    j = (int)((idx & 1023) << 2);
    const float4 a = *(const float4*)(hb + r * (2 * M) + j);
    const float4 z = *(const float4*)(hb + r * (2 * M) + M + j);
    float4 o;
    o.x = a.x * z.x / (1.f + __expf(-z.x));
    o.y = a.y * z.y / (1.f + __expf(-z.y));
    o.z = a.z * z.z / (1.f + __expf(-z.z));
    o.w = a.w * z.w / (1.f + __expf(-z.w));
    *(float4*)(act + r * M + j) = o;
}

// ---------------- launch ------------------------------------------------------
extern "C" void kernel_launch(void* const* d_in, const int* in_sizes, int n_in,
                              void* d_out, int out_size)
{
    const float* x       = (const float*)d_in[0];
    const float* emb     = (const float*)d_in[1];
    const float* ln1_w   = (const float*)d_in[2];
    const float* ln1_lW  = (const float*)d_in[3];
    const float* ln1_lb  = (const float*)d_in[4];
    const float* ln2_w   = (const float*)d_in[5];
    const float* ln2_lW  = (const float*)d_in[6];
    const float* ln2_lb  = (const float*)d_in[7];
    const float* qkv_W   = (const float*)d_in[8];
    const float* qkv_b   = (const float*)d_in[9];
    const float* proj_W  = (const float*)d_in[10];
    const float* proj_b  = (const float*)d_in[11];
    const float* nq_w    = (const float*)d_in[12];
    const float* nk_w    = (const float*)d_in[13];
    const float* mlp_W   = (const float*)d_in[14];
    const float* mlp_b   = (const float*)d_in[15];
    const float* out_W   = (const float*)d_in[16];
    const float* out_b   = (const float*)d_in[17];
    const float* gates_W = (const float*)d_in[18];
    const float* gates_b = (const float*)d_in[19];
    float* outp = (float*)d_out;

    float *xn, *qkv, *scores, *ao, *xmid, *hb, *act, *ss1, *ss2, *gates;
    cudaGetSymbolAddress((void**)&xn,     g_xn);
    cudaGetSymbolAddress((void**)&qkv,    g_qkv);
    cudaGetSymbolAddress((void**)&scores, g_scores);
    cudaGetSymbolAddress((void**)&ao,     g_ao);
    cudaGetSymbolAddress((void**)&xmid,   g_xmid);
    cudaGetSymbolAddress((void**)&hb,     g_h);
    cudaGetSymbolAddress((void**)&act,    g_act);
    cudaGetSymbolAddress((void**)&ss1,    g_ss1);
    cudaGetSymbolAddress((void**)&ss2,    g_ss2);
    cudaGetSymbolAddress((void**)&gates,  g_gates);

    // gates / ss1 / ss2 (all emb @ [E, 2D] + bias)
    emb_gemm3_kernel<<<dim3(2 * D / 64, B, 3), 256>>>(emb,
        gates_W, gates_b, gates,
        ln1_lW,  ln1_lb,  ss1,
        ln2_lW,  ln2_lb,  ss2);

    // xn = adaLN(x, ss1)
    adaln_kernel<<<BS, 256>>>(x, ss1, ln1_w, xn);

    // qkv = xn @ qkv_W + qkv_b
    gemm_kernel<0><<<dim3(3 * D / 128, BS / 128), 256>>>(xn, qkv_W, qkv_b, qkv,
                                                         3 * D, D, nullptr, nullptr);

    // rope + head rmsnorm on q, k (in place)
    rope_rms_kernel<<<BS * 2 * H, 64>>>(qkv, nq_w, nk_w);

    // attention
    attn_scores_kernel<<<dim3(S / 64, S / 64, B * H), 256>>>(qkv, scores);
    softmax_kernel<<<B * H * S, 256>>>(scores);
    attn_av_kernel<<<dim3(S / 64, B * H), 256>>>(scores, qkv, ao);

    // xmid = x + gate_mha * (ao @ proj_W + proj_b)
    gemm_kernel<1><<<dim3(D / 128, BS / 128), 256>>>(ao, proj_W, proj_b, xmid,
                                                     D, D, x, gates);

    // xn2 = adaLN(xmid, ss2)
    adaln_kernel<<<BS, 256>>>(xmid, ss2, ln2_w, xn);

    // h = xn2 @ mlp_W + mlp_b
    gemm_kernel<0><<<dim3(2 * M / 128, BS / 128), 256>>>(xn, mlp_W, mlp_b, hb,
                                                         2 * M, D, nullptr, nullptr);

    // act = h[:, :M] * silu(h[:, M:])
    silu_kernel<<<(int)((size_t)BS * M / 4 / 256), 256>>>(hb, act);

    // out = xmid + gate_mlp * (act @ out_W + out_b)
    gemm_kernel<1><<<dim3(D / 128, BS / 128), 256>>>(act, out_W, out_b, outp,
                                                     D, M, xmid, gates + D);
}